// round 14
// baseline (speedup 1.0000x reference)
#include <cuda_runtime.h>
#include <cuda_fp16.h>
#include <cstdint>
#include <cstddef>

// out_f32 = f16( f16(A[2048x4096] @ Wp[4096x4096]) @ Wu[4096x16384] )
// Legacy HMMA (tcgen05 rejected by harness ptxas). R14: B operands are read
// fp32-direct from the harness buffers; fp32->fp16 conversion happens inside
// the GEMM pipeline (one tile ahead), eliminating the Wp/Wu pre-conversion
// kernels (~400MB of HBM streaming).

#define BM 128
#define BN 256
#define BK 32
#define PAD 8
#define A_STRIDE (BK + PAD)            // 40 halves
#define BH_STRIDE (BN + PAD)           // 264 halves (fp16 B)
#define BF_STRIDE 256                  // floats per fp32 staging row (no pad)

#define A_STAGE_BYTES  (BM * A_STRIDE * 2)        // 10240
#define BF_STAGE_BYTES (BK * BF_STRIDE * 4)       // 32768
#define BH_BUF_BYTES   (BK * BH_STRIDE * 2)       // 16896
#define SMEM_A_OFF  0
#define SMEM_BF_OFF (3 * A_STAGE_BYTES)                    // 30720
#define SMEM_BH_OFF (SMEM_BF_OFF + 3 * BF_STAGE_BYTES)     // 129024
#define SMEM_DYN    (SMEM_BH_OFF + 2 * BH_BUF_BYTES)       // 162816

__device__ __half g_A  [8388608];   // fp16 A_prev
__device__ __half g_act[8388608];   // fp16 intermediate

__device__ __forceinline__ uint32_t smem_u32(const void* p) {
    return (uint32_t)__cvta_generic_to_shared(p);
}

// ---------------------------------------------------------------------------
__global__ void conv_A(const float4* __restrict__ src, int n4) {
    __half2* dst = (__half2*)g_A;
    const int stride = gridDim.x * blockDim.x;
    for (int i = blockIdx.x * blockDim.x + threadIdx.x; i < n4; i += stride) {
        float4 v = src[i];
        dst[2 * i + 0] = __floats2half2_rn(v.x, v.y);
        dst[2 * i + 1] = __floats2half2_rn(v.z, v.w);
    }
}

// ---------------------------------------------------------------------------
// fp16 GEMM: CTA 128x256, 16 warps as 2(M) x 8(N), warp tile 64x32, BK=32.
// A: fp16 global (g_A or g_act). B: fp32 global, converted in-pipeline.
template<bool STAGE2>
__global__ __launch_bounds__(512, 1) void gemm_f16_mma(
    const float* __restrict__ Bg, float* __restrict__ Cout, int M, int N, int K)
{
    extern __shared__ char smem[];
    const uint32_t sbA  = smem_u32(smem) + SMEM_A_OFF;
    const uint32_t sbBF = smem_u32(smem) + SMEM_BF_OFF;
    const uint32_t sbBH = smem_u32(smem) + SMEM_BH_OFF;

    const __half* Ag = STAGE2 ? (const __half*)g_act : (const __half*)g_A;

    const int tid  = threadIdx.x;
    const int lane = tid & 31;
    const int warp = tid >> 5;
    const int wr   = warp & 1;    // 2 warps along M
    const int wc   = warp >> 1;   // 8 warps along N

    const int bm = blockIdx.y * BM;
    const int bn = blockIdx.x * BN;

    float acc[4][4][4];
    #pragma unroll
    for (int i = 0; i < 4; i++)
        #pragma unroll
        for (int j = 0; j < 4; j++)
            #pragma unroll
            for (int r = 0; r < 4; r++) acc[i][j][r] = 0.f;

    // Issue cp.async for tile kt into stage kt%3 (A fp16 + B fp32), 1 group.
    auto load_tiles = [&](int kt) {
        const int s  = kt % 3;
        const int k0 = kt * BK;
        uint32_t aBase  = sbA  + s * A_STAGE_BYTES;
        uint32_t bfBase = sbBF + s * BF_STAGE_BYTES;
        {   // A: 128 rows x 64 B = 512 x 16B chunks (1/thread)
            int row = tid >> 2;
            int col = (tid & 3) << 3;
            uint32_t dst = aBase + (uint32_t)(row * A_STRIDE + col) * 2;
            const __half* src = Ag + (size_t)(bm + row) * K + (k0 + col);
            asm volatile("cp.async.cg.shared.global [%0], [%1], 16;"
                         :: "r"(dst), "l"(src) : "memory");
        }
        #pragma unroll
        for (int i = 0; i < 4; i++) {   // B fp32: 32 rows x 1024 B = 2048 chunks
            int t   = tid + i * 512;
            int row = t >> 6;
            int col = (t & 63) << 2;    // float index
            uint32_t dst = bfBase + (uint32_t)(row * BF_STRIDE + col) * 4;
            const float* src = Bg + (size_t)(k0 + row) * N + (bn + col);
            asm volatile("cp.async.cg.shared.global [%0], [%1], 16;"
                         :: "r"(dst), "l"(src) : "memory");
        }
        asm volatile("cp.async.commit_group;" ::: "memory");
    };

    // Convert tile kt's fp32 B staging -> fp16 buffer (kt&1).
    // Thread layout: 16 threads per row (rows 0..31), conflict-free phases.
    auto convert_B = [&](int kt) {
        const int s = kt % 3;
        uint32_t bfBase = sbBF + s * BF_STAGE_BYTES;
        uint32_t bhBase = sbBH + (kt & 1) * BH_BUF_BYTES;
        int row = tid >> 4;            // 0..31
        int k16 = tid & 15;            // 0..15
        #pragma unroll
        for (int j = 0; j < 4; j++) {
            int col = k16 * 4 + j * 64;    // float col
            float4 v = *(const float4*)(smem + (bfBase - smem_u32(smem)) +
                                        (size_t)(row * BF_STRIDE + col) * 4);
            __half2 h0 = __floats2half2_rn(v.x, v.y);
            __half2 h1 = __floats2half2_rn(v.z, v.w);
            *(__half2*)(smem + (bhBase - smem_u32(smem)) +
                        (size_t)(row * BH_STRIDE + col) * 2) = h0;
            *(__half2*)(smem + (bhBase - smem_u32(smem)) +
                        (size_t)(row * BH_STRIDE + col + 2) * 2) = h1;
        }
    };

    const int ntiles = K / BK;   // 128

    // Prologue: tiles 0 and 1 in flight; convert tile 0.
    load_tiles(0);
    load_tiles(1);
    asm volatile("cp.async.wait_group 1;" ::: "memory");
    __syncthreads();
    convert_B(0);

    for (int kt = 0; kt < ntiles; kt++) {
        __syncthreads();               // publish fp16(kt); guard stage reuse
        if (kt + 2 < ntiles) load_tiles(kt + 2);

        // MMA on tile kt: A from stage kt%3, B from fp16 buf kt&1.
        uint32_t aBase  = sbA  + (kt % 3) * A_STAGE_BYTES;
        uint32_t bhBase = sbBH + (kt & 1) * BH_BUF_BYTES;
        #pragma unroll
        for (int ks = 0; ks < 2; ks++) {          // 2 x k16 per BK=32
            uint32_t a[4][4];
            uint32_t b[2][4];
            #pragma unroll
            for (int i = 0; i < 4; i++) {
                int row = wr * 64 + i * 16 + (lane & 15);
                int col = ks * 16 + ((lane >> 4) << 3);
                uint32_t addr = aBase + (uint32_t)(row * A_STRIDE + col) * 2;
                asm volatile("ldmatrix.sync.aligned.m8n8.x4.shared.b16 {%0,%1,%2,%3}, [%4];"
                             : "=r"(a[i][0]), "=r"(a[i][1]), "=r"(a[i][2]), "=r"(a[i][3])
                             : "r"(addr));
            }
            #pragma unroll
            for (int jj = 0; jj < 2; jj++) {
                int row = ks * 16 + (lane & 15);
                int col = wc * 32 + jj * 16 + ((lane >> 4) << 3);
                uint32_t addr = bhBase + (uint32_t)(row * BH_STRIDE + col) * 2;
                asm volatile("ldmatrix.sync.aligned.m8n8.x4.trans.shared.b16 {%0,%1,%2,%3}, [%4];"
                             : "=r"(b[jj][0]), "=r"(b[jj][1]), "=r"(b[jj][2]), "=r"(b[jj][3])
                             : "r"(addr));
            }
            #pragma unroll
            for (int i = 0; i < 4; i++)
                #pragma unroll
                for (int j = 0; j < 4; j++) {
                    const uint32_t b0 = b[j >> 1][(j & 1) * 2 + 0];
                    const uint32_t b1 = b[j >> 1][(j & 1) * 2 + 1];
                    asm volatile(
                        "mma.sync.aligned.m16n8k16.row.col.f32.f16.f16.f32 "
                        "{%0,%1,%2,%3}, {%4,%5,%6,%7}, {%8,%9}, {%0,%1,%2,%3};"
                        : "+f"(acc[i][j][0]), "+f"(acc[i][j][1]),
                          "+f"(acc[i][j][2]), "+f"(acc[i][j][3])
                        : "r"(a[i][0]), "r"(a[i][1]), "r"(a[i][2]), "r"(a[i][3]),
                          "r"(b0), "r"(b1));
                }
        }

        // Ensure tile kt+1 has landed, then convert its B to fp16 buf.
        if (kt + 1 < ntiles) {
            asm volatile("cp.async.wait_group 1;" ::: "memory");
            convert_B(kt + 1);
        }
    }

    // Epilogue: fp32 acc -> fp16 round (bit-matches reference astype(float16)).
    #pragma unroll
    for (int i = 0; i < 4; i++) {
        #pragma unroll
        for (int j = 0; j < 4; j++) {
            int row0 = bm + wr * 64 + i * 16 + (lane >> 2);
            int col  = bn + wc * 32 + j * 8 + (lane & 3) * 2;
            __half2 h01 = __floats2half2_rn(acc[i][j][0], acc[i][j][1]);
            __half2 h23 = __floats2half2_rn(acc[i][j][2], acc[i][j][3]);
            if (!STAGE2) {
                *(__half2*)(g_act + (size_t)row0 * N + col) = h01;
                *(__half2*)(g_act + (size_t)(row0 + 8) * N + col) = h23;
            } else {
                *(float2*)(Cout + (size_t)row0 * N + col) =
                    make_float2(__half2float(__low2half(h01)), __half2float(__high2half(h01)));
                *(float2*)(Cout + (size_t)(row0 + 8) * N + col) =
                    make_float2(__half2float(__low2half(h23)), __half2float(__high2half(h23)));
            }
        }
    }
}

extern "C" void kernel_launch(void* const* d_in, const int* in_sizes, int n_in,
                              void* d_out, int out_size)
{
    (void)out_size;
    const float* A  = (const float*)d_in[0];
    const float* Wp = (n_in > 1) ? (const float*)d_in[1] : A;
    const float* Wu = (n_in > 2) ? (const float*)d_in[2] : A;
    for (int i = 0; i < n_in; i++) {
        if      (in_sizes[i] == 8388608)  A  = (const float*)d_in[i];
        else if (in_sizes[i] == 16777216) Wp = (const float*)d_in[i];
        else if (in_sizes[i] == 67108864) Wu = (const float*)d_in[i];
    }
    float* out = (float*)d_out;  // [2048, 16384] float32

    cudaFuncSetAttribute(gemm_f16_mma<false>,
                         cudaFuncAttributeMaxDynamicSharedMemorySize, SMEM_DYN);
    cudaFuncSetAttribute(gemm_f16_mma<true>,
                         cudaFuncAttributeMaxDynamicSharedMemorySize, SMEM_DYN);

    const int Bdim = 2048, Ddim = 4096, Kdim = 4096, Fdim = 16384;
    dim3 blk(512);

    conv_A<<<1024, 256>>>((const float4*)A, 8388608 / 4);

    // GEMM1: g_act = f16(A @ Wp), Wp read fp32-direct
    gemm_f16_mma<false><<<dim3(Ddim / BN, Bdim / BM), blk, SMEM_DYN>>>(
        Wp, nullptr, Bdim, Ddim, Kdim);
    // GEMM2: out = f16(g_act @ Wu), Wu read fp32-direct, fp32 store
    gemm_f16_mma<true><<<dim3(Fdim / BN, Bdim / BM), blk, SMEM_DYN>>>(
        Wu, out, Bdim, Fdim, Ddim);
}

// round 15
// speedup vs baseline: 1.2904x; 1.2904x over previous
#include <cuda_runtime.h>
#include <cuda_fp16.h>
#include <cstdint>
#include <cstddef>

// out_f32 = f16( f16(A[2048x4096] @ Wp[4096x4096]) @ Wu[4096x16384] )
// Legacy HMMA (tcgen05 rejected by harness ptxas target compute_103).
// R15: GEMM cores identical to R13 (best). conv_Wu is forked onto a second
// stream and overlaps conv_A/conv_Wp/GEMM1 (graph-capturable fork-join).

#define BM 128
#define BN 256
#define BK 64
#define STAGES 3
#define PAD 8
#define A_STRIDE (BK + PAD)            // 72 halves
#define B_STRIDE (BN + PAD)            // 264 halves

#define A_STAGE_BYTES (BM * A_STRIDE * 2)                 // 18432
#define B_STAGE_BYTES (BK * B_STRIDE * 2)                 // 33792
#define SMEM_A_OFF    0
#define SMEM_B_OFF    (STAGES * A_STAGE_BYTES)
#define SMEM_DYN      (STAGES * (A_STAGE_BYTES + B_STAGE_BYTES))  // 156672

__device__ __half g_A  [8388608];   // fp16 A_prev
__device__ __half g_Wp [16777216];  // fp16 W_prev
__device__ __half g_Wu [67108864];  // fp16 W_up
__device__ __half g_act[8388608];   // fp16 intermediate

__device__ __forceinline__ uint32_t smem_u32(const void* p) {
    return (uint32_t)__cvta_generic_to_shared(p);
}

// ---------------------------------------------------------------------------
template<int WHICH>
__global__ void f32_to_f16(const float4* __restrict__ src, int n4) {
    __half2* dst = (__half2*)((WHICH == 0) ? g_A : (WHICH == 1) ? g_Wp : g_Wu);
    const int stride = gridDim.x * blockDim.x;
    for (int i = blockIdx.x * blockDim.x + threadIdx.x; i < n4; i += stride) {
        float4 v = src[i];
        dst[2 * i + 0] = __floats2half2_rn(v.x, v.y);
        dst[2 * i + 1] = __floats2half2_rn(v.z, v.w);
    }
}

// ---------------------------------------------------------------------------
// fp16 GEMM: CTA 128x256, 16 warps as 2(M) x 8(N), warp tile 64x32.  (= R13)
template<bool STAGE2>
__global__ __launch_bounds__(512, 1) void gemm_f16_mma(
    float* __restrict__ Cout, int M, int N, int K)
{
    extern __shared__ char smem[];
    const uint32_t sbA = smem_u32(smem) + SMEM_A_OFF;
    const uint32_t sbB = smem_u32(smem) + SMEM_B_OFF;

    const __half* A  = STAGE2 ? (const __half*)g_act : (const __half*)g_A;
    const __half* Bm = STAGE2 ? (const __half*)g_Wu  : (const __half*)g_Wp;

    const int tid  = threadIdx.x;
    const int lane = tid & 31;
    const int warp = tid >> 5;
    const int wr   = warp & 1;
    const int wc   = warp >> 1;

    const int bm = blockIdx.y * BM;
    const int bn = blockIdx.x * BN;

    float acc[4][4][4];
    #pragma unroll
    for (int i = 0; i < 4; i++)
        #pragma unroll
        for (int j = 0; j < 4; j++)
            #pragma unroll
            for (int r = 0; r < 4; r++) acc[i][j][r] = 0.f;

    auto load_tiles = [&](int s, int k0) {
        uint32_t aBase = sbA + s * A_STAGE_BYTES;
        uint32_t bBase = sbB + s * B_STAGE_BYTES;
        #pragma unroll
        for (int i = 0; i < 2; i++) {            // A: 1024 x 16B chunks
            int t   = tid + i * 512;
            int row = t >> 3;
            int col = (t & 7) << 3;
            uint32_t dst = aBase + (uint32_t)(row * A_STRIDE + col) * 2;
            const __half* src = A + (size_t)(bm + row) * K + (k0 + col);
            asm volatile("cp.async.cg.shared.global [%0], [%1], 16;"
                         :: "r"(dst), "l"(src) : "memory");
        }
        #pragma unroll
        for (int i = 0; i < 4; i++) {            // B: 2048 x 16B chunks
            int t   = tid + i * 512;
            int row = t >> 5;
            int col = (t & 31) << 3;
            uint32_t dst = bBase + (uint32_t)(row * B_STRIDE + col) * 2;
            const __half* src = Bm + (size_t)(k0 + row) * N + (bn + col);
            asm volatile("cp.async.cg.shared.global [%0], [%1], 16;"
                         :: "r"(dst), "l"(src) : "memory");
        }
        asm volatile("cp.async.commit_group;" ::: "memory");
    };

    const int ntiles = K / BK;   // 64

    #pragma unroll
    for (int s = 0; s < STAGES - 1; s++)
        load_tiles(s, s * BK);

    for (int kt = 0; kt < ntiles; kt++) {
        const int s = kt % STAGES;
        asm volatile("cp.async.wait_group %0;" :: "n"(STAGES - 2) : "memory");
        __syncthreads();
        if (kt + STAGES - 1 < ntiles)
            load_tiles((kt + STAGES - 1) % STAGES, (kt + STAGES - 1) * BK);

        uint32_t aBase = sbA + s * A_STAGE_BYTES;
        uint32_t bBase = sbB + s * B_STAGE_BYTES;

        #pragma unroll
        for (int ks = 0; ks < 4; ks++) {          // 4 x k16 per BK=64
            uint32_t a[4][4];
            uint32_t b[2][4];
            #pragma unroll
            for (int i = 0; i < 4; i++) {
                int row = wr * 64 + i * 16 + (lane & 15);
                int col = ks * 16 + ((lane >> 4) << 3);
                uint32_t addr = aBase + (uint32_t)(row * A_STRIDE + col) * 2;
                asm volatile("ldmatrix.sync.aligned.m8n8.x4.shared.b16 {%0,%1,%2,%3}, [%4];"
                             : "=r"(a[i][0]), "=r"(a[i][1]), "=r"(a[i][2]), "=r"(a[i][3])
                             : "r"(addr));
            }
            #pragma unroll
            for (int jj = 0; jj < 2; jj++) {
                int row = ks * 16 + (lane & 15);
                int col = wc * 32 + jj * 16 + ((lane >> 4) << 3);
                uint32_t addr = bBase + (uint32_t)(row * B_STRIDE + col) * 2;
                asm volatile("ldmatrix.sync.aligned.m8n8.x4.trans.shared.b16 {%0,%1,%2,%3}, [%4];"
                             : "=r"(b[jj][0]), "=r"(b[jj][1]), "=r"(b[jj][2]), "=r"(b[jj][3])
                             : "r"(addr));
            }
            #pragma unroll
            for (int i = 0; i < 4; i++)
                #pragma unroll
                for (int j = 0; j < 4; j++) {
                    const uint32_t b0 = b[j >> 1][(j & 1) * 2 + 0];
                    const uint32_t b1 = b[j >> 1][(j & 1) * 2 + 1];
                    asm volatile(
                        "mma.sync.aligned.m16n8k16.row.col.f32.f16.f16.f32 "
                        "{%0,%1,%2,%3}, {%4,%5,%6,%7}, {%8,%9}, {%0,%1,%2,%3};"
                        : "+f"(acc[i][j][0]), "+f"(acc[i][j][1]),
                          "+f"(acc[i][j][2]), "+f"(acc[i][j][3])
                        : "r"(a[i][0]), "r"(a[i][1]), "r"(a[i][2]), "r"(a[i][3]),
                          "r"(b0), "r"(b1));
                }
        }
    }

    // Epilogue: fp32 acc -> fp16 round (bit-matches reference astype(float16)).
    #pragma unroll
    for (int i = 0; i < 4; i++) {
        #pragma unroll
        for (int j = 0; j < 4; j++) {
            int row0 = bm + wr * 64 + i * 16 + (lane >> 2);
            int col  = bn + wc * 32 + j * 8 + (lane & 3) * 2;
            __half2 h01 = __floats2half2_rn(acc[i][j][0], acc[i][j][1]);
            __half2 h23 = __floats2half2_rn(acc[i][j][2], acc[i][j][3]);
            if (!STAGE2) {
                *(__half2*)(g_act + (size_t)row0 * N + col) = h01;
                *(__half2*)(g_act + (size_t)(row0 + 8) * N + col) = h23;
            } else {
                *(float2*)(Cout + (size_t)row0 * N + col) =
                    make_float2(__half2float(__low2half(h01)), __half2float(__high2half(h01)));
                *(float2*)(Cout + (size_t)(row0 + 8) * N + col) =
                    make_float2(__half2float(__low2half(h23)), __half2float(__high2half(h23)));
            }
        }
    }
}

extern "C" void kernel_launch(void* const* d_in, const int* in_sizes, int n_in,
                              void* d_out, int out_size)
{
    (void)out_size;
    const float* A  = (const float*)d_in[0];
    const float* Wp = (n_in > 1) ? (const float*)d_in[1] : A;
    const float* Wu = (n_in > 2) ? (const float*)d_in[2] : A;
    for (int i = 0; i < n_in; i++) {
        if      (in_sizes[i] == 8388608)  A  = (const float*)d_in[i];
        else if (in_sizes[i] == 16777216) Wp = (const float*)d_in[i];
        else if (in_sizes[i] == 67108864) Wu = (const float*)d_in[i];
    }
    float* out = (float*)d_out;  // [2048, 16384] float32

    cudaFuncSetAttribute(gemm_f16_mma<false>,
                         cudaFuncAttributeMaxDynamicSharedMemorySize, SMEM_DYN);
    cudaFuncSetAttribute(gemm_f16_mma<true>,
                         cudaFuncAttributeMaxDynamicSharedMemorySize, SMEM_DYN);

    // Lazily created once (first call runs outside graph capture). Stream and
    // events are reused on every call: no per-call resource churn and no
    // device-memory allocation.
    static cudaStream_t s2 = nullptr;
    static cudaEvent_t  evFork = nullptr, evJoin = nullptr;
    if (s2 == nullptr) {
        cudaStreamCreateWithFlags(&s2, cudaStreamNonBlocking);
        cudaEventCreateWithFlags(&evFork, cudaEventDisableTiming);
        cudaEventCreateWithFlags(&evJoin, cudaEventDisableTiming);
    }

    const int Bdim = 2048, Ddim = 4096, Kdim = 4096, Fdim = 16384;
    dim3 blk(512);

    // Fork: conv_Wu runs on s2, overlapping conv_A + conv_Wp + GEMM1.
    cudaEventRecord(evFork, 0);
    cudaStreamWaitEvent(s2, evFork, 0);
    f32_to_f16<2><<<4096, 256, 0, s2>>>((const float4*)Wu, 67108864 / 4);
    cudaEventRecord(evJoin, s2);

    // Main stream: A and Wp conversions, then GEMM1 (none touch Wu).
    f32_to_f16<0><<<1024, 256>>>((const float4*)A,  8388608  / 4);
    f32_to_f16<1><<<2048, 256>>>((const float4*)Wp, 16777216 / 4);
    gemm_f16_mma<false><<<dim3(Ddim / BN, Bdim / BM), blk, SMEM_DYN>>>(nullptr, Bdim, Ddim, Kdim);

    // Join: GEMM2 needs g_Wu (and g_act from GEMM1).
    cudaStreamWaitEvent(0, evJoin, 0);
    gemm_f16_mma<true><<<dim3(Fdim / BN, Bdim / BM), blk, SMEM_DYN>>>(out, Bdim, Fdim, Ddim);
}